// round 2
// baseline (speedup 1.0000x reference)
#include <cuda_runtime.h>
#include <mma.h>
#include <math.h>

using namespace nvcuda;

// ---------------- problem constants ----------------
#define TOK     65536          // 16 * 64 * 64 tokens
#define EMBED   512
#define HEADS   16
#define HD      32
#define FFN     2048
#define SHIFT   4
#define NWIN    1024           // total windows (16 images * 64)
constexpr float SCALE = 0.17677669529663687f;   // 32^-0.5

// ---------------- device scratch (static: allocation-guard safe) ----------------
__device__ __align__(256) float g_lnx [(size_t)TOK * EMBED];
__device__ __align__(256) float g_lns [(size_t)TOK * EMBED];
__device__ __align__(256) float g_kv  [(size_t)TOK * 2 * EMBED];
__device__ __align__(256) float g_qh  [(size_t)TOK * EMBED];
__device__ __align__(256) float g_att [(size_t)TOK * EMBED];
__device__ __align__(256) float g_xres[(size_t)TOK * EMBED];
__device__ __align__(256) float g_ln2 [(size_t)TOK * EMBED];
__device__ __align__(256) float g_ffn [(size_t)TOK * FFN];

// windowed token index -> original token index (handles roll by -SHIFT both ways:
// gather source for LN, scatter destination for proj output — same formula)
__device__ __forceinline__ int remap_token(int wt) {
    int win = wt >> 6, n = wt & 63;
    int b  = win >> 6, wi = win & 63;
    int wr = wi >> 3,  wc = wi & 7;
    int r  = n  >> 3,  cc = n  & 7;
    int grow = (wr * 8 + r  + SHIFT) & 63;
    int gcol = (wc * 8 + cc + SHIFT) & 63;
    return (b << 12) + (grow << 6) + gcol;
}

// ---------------- block reduce (128 threads) ----------------
__device__ __forceinline__ float blockReduce128(float v, float* red) {
    #pragma unroll
    for (int o = 16; o > 0; o >>= 1) v += __shfl_xor_sync(0xffffffffu, v, o);
    int lane = threadIdx.x & 31, w = threadIdx.x >> 5;
    if (lane == 0) red[w] = v;
    __syncthreads();
    float r = red[0] + red[1] + red[2] + red[3];
    __syncthreads();
    return r;
}

// ---------------- LayerNorm kernels ----------------
// GATHER=true : grid (TOK, 2), y==0: x -> g_lnx (window order), y==1: skip -> g_lns
// GATHER=false: grid (TOK, 1), g_xres -> g_ln2 (original token order)
template<bool GATHER>
__global__ __launch_bounds__(128)
void ln_kernel(const float* __restrict__ src_x, const float* __restrict__ src_s,
               const float* __restrict__ g, const float* __restrict__ b)
{
    __shared__ float red[4];
    int wt = blockIdx.x;
    const float* src;
    float* dst;
    if constexpr (GATHER) {
        int ot = remap_token(wt);
        src = (blockIdx.y == 0 ? src_x : src_s) + (size_t)ot * EMBED;
        dst = (blockIdx.y == 0 ? g_lnx : g_lns) + (size_t)wt * EMBED;
    } else {
        src = g_xres + (size_t)wt * EMBED;
        dst = g_ln2  + (size_t)wt * EMBED;
    }
    int t = threadIdx.x;
    float4 v = *(const float4*)&src[t * 4];
    float sum  = blockReduce128(v.x + v.y + v.z + v.w, red);
    float mean = sum * (1.0f / 512.0f);
    float dx = v.x - mean, dy = v.y - mean, dz = v.z - mean, dw = v.w - mean;
    float var = blockReduce128(dx*dx + dy*dy + dz*dz + dw*dw, red) * (1.0f / 512.0f);
    float rs = rsqrtf(var + 1e-5f);
    float4 gg = *(const float4*)&g[t * 4];
    float4 bb = *(const float4*)&b[t * 4];
    float4 o;
    o.x = dx * rs * gg.x + bb.x;
    o.y = dy * rs * gg.y + bb.y;
    o.z = dz * rs * gg.z + bb.z;
    o.w = dw * rs * gg.w + bb.w;
    *(float4*)&dst[t * 4] = o;
}

// ---------------- GEMM (tf32 wmma, NT: C[M,N] = A[M,K] * W[N,K]^T) ----------------
constexpr int BM = 128, BN = 64, BK = 32, SPITCH = 36;

enum { EP_KV = 0, EP_QH = 1, EP_PROJ = 2, EP_FC1 = 3, EP_FC2 = 4 };

__device__ __forceinline__ float gelu_exact(float x) {
    return 0.5f * x * (1.0f + erff(x * 0.7071067811865475f));
}

template<int MODE>
__global__ __launch_bounds__(256)
void gemm_tf32(const float* __restrict__ Bw, const float* __restrict__ bias,
               const float* __restrict__ extra, float* __restrict__ out_param,
               int K, int ldo)
{
    extern __shared__ __align__(16) float smem[];
    float* sA = smem;                      // BM*SPITCH
    float* sB = smem + BM * SPITCH;        // BN*SPITCH
    float* sC = smem;                      // reuse for epilogue (BM*BN)

    const float* A;
    float* outp;
    if constexpr (MODE == EP_KV)        { A = g_lnx; outp = g_kv;   }
    else if constexpr (MODE == EP_QH)   { A = g_lns; outp = g_qh;   }
    else if constexpr (MODE == EP_PROJ) { A = g_att; outp = g_xres; }
    else if constexpr (MODE == EP_FC1)  { A = g_ln2; outp = g_ffn;  }
    else                                { A = g_ffn; outp = out_param; }

    const int tid   = threadIdx.x;
    const int tileM = blockIdx.y * BM;
    const int tileN = blockIdx.x * BN;
    const int warp  = tid >> 5;
    const int wm    = warp >> 1;   // 0..3
    const int wn    = warp & 1;    // 0..1

    wmma::fragment<wmma::accumulator, 16, 16, 8, float> acc[2][2];
    #pragma unroll
    for (int i = 0; i < 2; i++)
        #pragma unroll
        for (int j = 0; j < 2; j++)
            wmma::fill_fragment(acc[i][j], 0.0f);

    for (int k0 = 0; k0 < K; k0 += BK) {
        #pragma unroll
        for (int it = 0; it < 4; it++) {
            int idx = tid + it * 256;
            int row = idx >> 3, q = idx & 7;
            *(float4*)&sA[row * SPITCH + q * 4] =
                *(const float4*)&A[(size_t)(tileM + row) * K + k0 + q * 4];
        }
        #pragma unroll
        for (int it = 0; it < 2; it++) {
            int idx = tid + it * 256;
            int row = idx >> 3, q = idx & 7;
            *(float4*)&sB[row * SPITCH + q * 4] =
                *(const float4*)&Bw[(size_t)(tileN + row) * K + k0 + q * 4];
        }
        __syncthreads();
        #pragma unroll
        for (int kk = 0; kk < BK; kk += 8) {
            wmma::fragment<wmma::matrix_a, 16, 16, 8, wmma::precision::tf32, wmma::row_major> fa[2];
            wmma::fragment<wmma::matrix_b, 16, 16, 8, wmma::precision::tf32, wmma::col_major> fb[2];
            #pragma unroll
            for (int i = 0; i < 2; i++) {
                wmma::load_matrix_sync(fa[i], &sA[(wm * 32 + i * 16) * SPITCH + kk], SPITCH);
                #pragma unroll
                for (int e = 0; e < fa[i].num_elements; e++)
                    fa[i].x[e] = wmma::__float_to_tf32(fa[i].x[e]);
            }
            #pragma unroll
            for (int j = 0; j < 2; j++) {
                wmma::load_matrix_sync(fb[j], &sB[(wn * 32 + j * 16) * SPITCH + kk], SPITCH);
                #pragma unroll
                for (int e = 0; e < fb[j].num_elements; e++)
                    fb[j].x[e] = wmma::__float_to_tf32(fb[j].x[e]);
            }
            #pragma unroll
            for (int i = 0; i < 2; i++)
                #pragma unroll
                for (int j = 0; j < 2; j++)
                    wmma::mma_sync(acc[i][j], fa[i], fb[j], acc[i][j]);
        }
        __syncthreads();
    }

    // ---- epilogue: stage C in smem, then per-element fused op ----
    #pragma unroll
    for (int i = 0; i < 2; i++)
        #pragma unroll
        for (int j = 0; j < 2; j++)
            wmma::store_matrix_sync(&sC[(wm * 32 + i * 16) * BN + wn * 32 + j * 16],
                                    acc[i][j], BN, wmma::mem_row_major);
    __syncthreads();

    #pragma unroll
    for (int it = 0; it < 8; it++) {
        int idx = tid + it * 256;          // 0..2047
        int row = idx >> 4;                // 0..127
        int col = (idx & 15) * 4;          // 0..60
        float4 v = *(float4*)&sC[row * BN + col];
        int gr = tileM + row;
        int gc = tileN + col;
        float4 bb = *(const float4*)&bias[gc];
        v.x += bb.x; v.y += bb.y; v.z += bb.z; v.w += bb.w;

        int orow = gr;
        if constexpr (MODE == EP_QH) {
            v.x *= SCALE; v.y *= SCALE; v.z *= SCALE; v.w *= SCALE;
        } else if constexpr (MODE == EP_PROJ) {
            orow = remap_token(gr);
            float4 id = *(const float4*)&extra[(size_t)orow * EMBED + gc];
            v.x += id.x; v.y += id.y; v.z += id.z; v.w += id.w;
        } else if constexpr (MODE == EP_FC1) {
            v.x = gelu_exact(v.x); v.y = gelu_exact(v.y);
            v.z = gelu_exact(v.z); v.w = gelu_exact(v.w);
        } else if constexpr (MODE == EP_FC2) {
            // final residual: x_after_attention (g_xres), resolved as device symbol
            const float* rsrc = g_xres;
            float4 rr = *(const float4*)&rsrc[(size_t)gr * EMBED + gc];
            v.x += rr.x; v.y += rr.y; v.z += rr.z; v.w += rr.w;
        }
        *(float4*)&outp[(size_t)orow * ldo + gc] = v;
    }
}

// ---------------- fused windowed attention ----------------
// one CTA per (window, head), 64 threads = one per query row
__global__ __launch_bounds__(64)
void attn_kernel(const float* __restrict__ relb)
{
    int head = blockIdx.x & (HEADS - 1);
    int win  = blockIdx.x >> 4;

    __shared__ __align__(16) float ks[64 * 36];
    __shared__ __align__(16) float vs[64 * 36];
    __shared__ int   lab[64];
    __shared__ int   crd[64];

    int n = threadIdx.x;
    const float* kp = &g_kv[((size_t)win * 64 + n) * 1024 + head * HD];
    #pragma unroll
    for (int q = 0; q < 8; q++) {
        *(float4*)&ks[n * 36 + q * 4] = *(const float4*)&kp[q * 4];
        *(float4*)&vs[n * 36 + q * 4] = *(const float4*)&kp[512 + q * 4];
    }
    float qreg[32];
    const float* qp = &g_qh[((size_t)win * 64 + n) * EMBED + head * HD];
    #pragma unroll
    for (int q = 0; q < 8; q++) {
        float4 t = *(const float4*)&qp[q * 4];
        qreg[q*4] = t.x; qreg[q*4+1] = t.y; qreg[q*4+2] = t.z; qreg[q*4+3] = t.w;
    }
    // shift-mask region labels (rolled-grid coords) + rel-pos coord
    {
        int wi = win & 63, wr = wi >> 3, wc = wi & 7;
        int r = n >> 3, cc = n & 7;
        int grow = wr * 8 + r, gcol = wc * 8 + cc;
        int lh = (grow < 56) ? 0 : ((grow < 60) ? 1 : 2);
        int lw = (gcol < 56) ? 0 : ((gcol < 60) ? 1 : 2);
        lab[n] = lh * 3 + lw;
        crd[n] = r * 15 + cc;
    }
    __syncthreads();

    int myLab = lab[n], myC = crd[n];
    float s[64];
    #pragma unroll
    for (int m = 0; m < 64; m++) {
        float a = 0.0f;
        #pragma unroll
        for (int d = 0; d < 32; d += 4) {
            float4 kk = *(const float4*)&ks[m * 36 + d];
            a = fmaf(qreg[d],   kk.x, a);
            a = fmaf(qreg[d+1], kk.y, a);
            a = fmaf(qreg[d+2], kk.z, a);
            a = fmaf(qreg[d+3], kk.w, a);
        }
        a += __ldg(&relb[(myC + crd[63 - m]) * HEADS + head]);
        if (lab[m] != myLab) a -= 100.0f;
        s[m] = a;
    }
    float mx = s[0];
    #pragma unroll
    for (int m = 1; m < 64; m++) mx = fmaxf(mx, s[m]);
    float sum = 0.0f;
    #pragma unroll
    for (int m = 0; m < 64; m++) { s[m] = expf(s[m] - mx); sum += s[m]; }
    float inv = 1.0f / sum;

    float o[32];
    #pragma unroll
    for (int d = 0; d < 32; d++) o[d] = 0.0f;
    #pragma unroll
    for (int m = 0; m < 64; m++) {
        float p = s[m];
        #pragma unroll
        for (int d = 0; d < 32; d += 4) {
            float4 vv = *(const float4*)&vs[m * 36 + d];
            o[d]   = fmaf(p, vv.x, o[d]);
            o[d+1] = fmaf(p, vv.y, o[d+1]);
            o[d+2] = fmaf(p, vv.z, o[d+2]);
            o[d+3] = fmaf(p, vv.w, o[d+3]);
        }
    }
    float* op = &g_att[((size_t)win * 64 + n) * EMBED + head * HD];
    #pragma unroll
    for (int d = 0; d < 32; d += 4) {
        float4 t;
        t.x = o[d] * inv; t.y = o[d+1] * inv; t.z = o[d+2] * inv; t.w = o[d+3] * inv;
        *(float4*)&op[d] = t;
    }
}

// ---------------- launch ----------------
extern "C" void kernel_launch(void* const* d_in, const int* in_sizes, int n_in,
                              void* d_out, int out_size)
{
    const float* x      = (const float*)d_in[0];
    const float* skip   = (const float*)d_in[1];
    const float* n1g    = (const float*)d_in[2];
    const float* n1b    = (const float*)d_in[3];
    const float* w_qkv  = (const float*)d_in[4];
    const float* b_qkv  = (const float*)d_in[5];
    const float* w_skip = (const float*)d_in[6];
    const float* b_skip = (const float*)d_in[7];
    const float* relb   = (const float*)d_in[8];
    const float* w_proj = (const float*)d_in[9];
    const float* b_proj = (const float*)d_in[10];
    const float* n2g    = (const float*)d_in[11];
    const float* n2b    = (const float*)d_in[12];
    const float* w_fc1  = (const float*)d_in[13];
    const float* b_fc1  = (const float*)d_in[14];
    const float* w_fc2  = (const float*)d_in[15];
    const float* b_fc2  = (const float*)d_in[16];
    float* out = (float*)d_out;

    const size_t smemB = (size_t)BM * BN * sizeof(float);   // 32 KB (covers A+B stage too)

    // 1) LN1 + shift-roll + window gather (x and skip)
    ln_kernel<true><<<dim3(TOK, 2), 128>>>(x, skip, n1g, n1b);
    // 2) kv = lnx @ w_qkv^T + b
    gemm_tf32<EP_KV><<<dim3(1024 / BN, TOK / BM), 256, smemB>>>(w_qkv, b_qkv, nullptr, nullptr, 512, 1024);
    // 3) q = (lns @ w_skip^T + b) * SCALE
    gemm_tf32<EP_QH><<<dim3(512 / BN, TOK / BM), 256, smemB>>>(w_skip, b_skip, nullptr, nullptr, 512, 512);
    // 4) fused attention per (window, head)
    attn_kernel<<<NWIN * HEADS, 64>>>(relb);
    // 5) proj + scatter back (inverse roll) + residual with original x
    gemm_tf32<EP_PROJ><<<dim3(512 / BN, TOK / BM), 256, smemB>>>(w_proj, b_proj, x, nullptr, 512, 512);
    // 6) LN2
    ln_kernel<false><<<dim3(TOK, 1), 128>>>(nullptr, nullptr, n2g, n2b);
    // 7) fc1 + exact GELU
    gemm_tf32<EP_FC1><<<dim3(FFN / BN, TOK / BM), 256, smemB>>>(w_fc1, b_fc1, nullptr, nullptr, 512, FFN);
    // 8) fc2 + residual -> d_out
    gemm_tf32<EP_FC2><<<dim3(512 / BN, TOK / BM), 256, smemB>>>(w_fc2, b_fc2, nullptr, out, FFN, 512);
}

// round 3
// speedup vs baseline: 1.0814x; 1.0814x over previous
#include <cuda_runtime.h>
#include <mma.h>
#include <math.h>

using namespace nvcuda;

// ---------------- problem constants ----------------
#define TOK     65536          // 16 * 64 * 64 tokens
#define EMBED   512
#define HEADS   16
#define HD      32
#define FFN     2048
#define SHIFT   4
#define NWIN    1024
constexpr float SCALE = 0.17677669529663687f;   // 32^-0.5

// ---------------- device scratch ----------------
__device__ __align__(256) float g_lnx [(size_t)TOK * EMBED];
__device__ __align__(256) float g_lns [(size_t)TOK * EMBED];
__device__ __align__(256) float g_kv  [(size_t)TOK * 2 * EMBED];
__device__ __align__(256) float g_qh  [(size_t)TOK * EMBED];
__device__ __align__(256) float g_att [(size_t)TOK * EMBED];
__device__ __align__(256) float g_xres[(size_t)TOK * EMBED];
__device__ __align__(256) float g_ln2 [(size_t)TOK * EMBED];
__device__ __align__(256) float g_ffn [(size_t)TOK * FFN];

__device__ __forceinline__ int remap_token(int wt) {
    int win = wt >> 6, n = wt & 63;
    int b  = win >> 6, wi = win & 63;
    int wr = wi >> 3,  wc = wi & 7;
    int r  = n  >> 3,  cc = n  & 7;
    int grow = (wr * 8 + r  + SHIFT) & 63;
    int gcol = (wc * 8 + cc + SHIFT) & 63;
    return (b << 12) + (grow << 6) + gcol;
}

__device__ __forceinline__ void cp_async16(float* smem_dst, const float* gsrc) {
    unsigned s = (unsigned)__cvta_generic_to_shared(smem_dst);
    asm volatile("cp.async.cg.shared.global [%0], [%1], 16;\n" :: "r"(s), "l"(gsrc));
}

// ---------------- block reduce (128 threads) ----------------
__device__ __forceinline__ float blockReduce128(float v, float* red) {
    #pragma unroll
    for (int o = 16; o > 0; o >>= 1) v += __shfl_xor_sync(0xffffffffu, v, o);
    int lane = threadIdx.x & 31, w = threadIdx.x >> 5;
    if (lane == 0) red[w] = v;
    __syncthreads();
    float r = red[0] + red[1] + red[2] + red[3];
    __syncthreads();
    return r;
}

// ---------------- LayerNorm kernels ----------------
template<bool GATHER>
__global__ __launch_bounds__(128)
void ln_kernel(const float* __restrict__ src_x, const float* __restrict__ src_s,
               const float* __restrict__ g, const float* __restrict__ b)
{
    __shared__ float red[4];
    int wt = blockIdx.x;
    const float* src;
    float* dst;
    if constexpr (GATHER) {
        int ot = remap_token(wt);
        src = (blockIdx.y == 0 ? src_x : src_s) + (size_t)ot * EMBED;
        dst = (blockIdx.y == 0 ? g_lnx : g_lns) + (size_t)wt * EMBED;
    } else {
        src = g_xres + (size_t)wt * EMBED;
        dst = g_ln2  + (size_t)wt * EMBED;
    }
    int t = threadIdx.x;
    float4 v = *(const float4*)&src[t * 4];
    float sum  = blockReduce128(v.x + v.y + v.z + v.w, red);
    float mean = sum * (1.0f / 512.0f);
    float dx = v.x - mean, dy = v.y - mean, dz = v.z - mean, dw = v.w - mean;
    float var = blockReduce128(dx*dx + dy*dy + dz*dz + dw*dw, red) * (1.0f / 512.0f);
    float rs = rsqrtf(var + 1e-5f);
    float4 gg = *(const float4*)&g[t * 4];
    float4 bb = *(const float4*)&b[t * 4];
    float4 o;
    o.x = dx * rs * gg.x + bb.x;
    o.y = dy * rs * gg.y + bb.y;
    o.z = dz * rs * gg.z + bb.z;
    o.w = dw * rs * gg.w + bb.w;
    *(float4*)&dst[t * 4] = o;
}

// ---------------- GEMM: tf32 wmma, cp.async double-buffered ----------------
// C[M,N] = A[M,K] * W[N,K]^T ; BM=128 BN=128 BK=32, 256 threads, warp tile 32x64
constexpr int BM = 128, BN = 128, BK = 32, SPITCH = 36;
constexpr int STAGE_FLOATS = (BM + BN) * SPITCH;            // 9216 floats / stage
constexpr size_t GEMM_SMEM = 2 * STAGE_FLOATS * sizeof(float);  // 73728 B

enum { EP_KV = 0, EP_QH = 1, EP_PROJ = 2, EP_FC1 = 3, EP_FC2 = 4 };

__device__ __forceinline__ float gelu_exact(float x) {
    return 0.5f * x * (1.0f + erff(x * 0.7071067811865475f));
}

template<int MODE>
__global__ __launch_bounds__(256, 2)
void gemm_tf32(const float* __restrict__ Bw, const float* __restrict__ bias,
               const float* __restrict__ extra, float* __restrict__ out_param,
               int K, int ldo)
{
    extern __shared__ __align__(16) float smem[];

    const float* A;
    float* outp;
    if constexpr (MODE == EP_KV)        { A = g_lnx; outp = g_kv;   }
    else if constexpr (MODE == EP_QH)   { A = g_lns; outp = g_qh;   }
    else if constexpr (MODE == EP_PROJ) { A = g_att; outp = g_xres; }
    else if constexpr (MODE == EP_FC1)  { A = g_ln2; outp = g_ffn;  }
    else                                { A = g_ffn; outp = out_param; }

    const int tid   = threadIdx.x;
    const int tileM = blockIdx.y * BM;
    const int tileN = blockIdx.x * BN;
    const int warp  = tid >> 5;
    const int wm    = warp >> 1;   // 0..3  -> rows wm*32
    const int wn    = warp & 1;    // 0..1  -> cols wn*64

    // stage loader: A tile 128x32 (1024 float4), B tile 128x32 (1024 float4)
    auto loadStage = [&](int s, int k0) {
        float* sA = smem + s * STAGE_FLOATS;
        float* sB = sA + BM * SPITCH;
        #pragma unroll
        for (int it = 0; it < 4; it++) {
            int idx = tid + it * 256;
            int row = idx >> 3, q = idx & 7;
            cp_async16(&sA[row * SPITCH + q * 4],
                       &A[(size_t)(tileM + row) * K + k0 + q * 4]);
        }
        #pragma unroll
        for (int it = 0; it < 4; it++) {
            int idx = tid + it * 256;
            int row = idx >> 3, q = idx & 7;
            cp_async16(&sB[row * SPITCH + q * 4],
                       &Bw[(size_t)(tileN + row) * K + k0 + q * 4]);
        }
        asm volatile("cp.async.commit_group;");
    };

    wmma::fragment<wmma::accumulator, 16, 16, 8, float> acc[2][4];
    #pragma unroll
    for (int i = 0; i < 2; i++)
        #pragma unroll
        for (int j = 0; j < 4; j++)
            wmma::fill_fragment(acc[i][j], 0.0f);

    const int nIter = K / BK;
    loadStage(0, 0);

    for (int i = 0; i < nIter; i++) {
        if (i + 1 < nIter) {
            loadStage((i + 1) & 1, (i + 1) * BK);
            asm volatile("cp.async.wait_group 1;");
        } else {
            asm volatile("cp.async.wait_group 0;");
        }
        __syncthreads();

        float* sA = smem + (i & 1) * STAGE_FLOATS;
        float* sB = sA + BM * SPITCH;

        #pragma unroll
        for (int kk = 0; kk < BK; kk += 8) {
            wmma::fragment<wmma::matrix_a, 16, 16, 8, wmma::precision::tf32, wmma::row_major> fa[2];
            wmma::fragment<wmma::matrix_b, 16, 16, 8, wmma::precision::tf32, wmma::col_major> fb[4];
            #pragma unroll
            for (int ii = 0; ii < 2; ii++) {
                wmma::load_matrix_sync(fa[ii], &sA[(wm * 32 + ii * 16) * SPITCH + kk], SPITCH);
                #pragma unroll
                for (int e = 0; e < fa[ii].num_elements; e++)
                    fa[ii].x[e] = wmma::__float_to_tf32(fa[ii].x[e]);
            }
            #pragma unroll
            for (int j = 0; j < 4; j++) {
                wmma::load_matrix_sync(fb[j], &sB[(wn * 64 + j * 16) * SPITCH + kk], SPITCH);
                #pragma unroll
                for (int e = 0; e < fb[j].num_elements; e++)
                    fb[j].x[e] = wmma::__float_to_tf32(fb[j].x[e]);
            }
            #pragma unroll
            for (int ii = 0; ii < 2; ii++)
                #pragma unroll
                for (int j = 0; j < 4; j++)
                    wmma::mma_sync(acc[ii][j], fa[ii], fb[j], acc[ii][j]);
        }
        __syncthreads();
    }

    // ---- epilogue: stage C (128x128) in smem, then fused per-element op ----
    float* sC = smem;
    #pragma unroll
    for (int i = 0; i < 2; i++)
        #pragma unroll
        for (int j = 0; j < 4; j++)
            wmma::store_matrix_sync(&sC[(wm * 32 + i * 16) * BN + wn * 64 + j * 16],
                                    acc[i][j], BN, wmma::mem_row_major);
    __syncthreads();

    #pragma unroll
    for (int it = 0; it < 16; it++) {
        int idx = tid + it * 256;          // 0..4095 (float4 units)
        int row = idx >> 5;                // 0..127
        int col = (idx & 31) * 4;          // 0..124
        float4 v = *(float4*)&sC[row * BN + col];
        int gr = tileM + row;
        int gc = tileN + col;
        float4 bb = *(const float4*)&bias[gc];
        v.x += bb.x; v.y += bb.y; v.z += bb.z; v.w += bb.w;

        int orow = gr;
        if constexpr (MODE == EP_QH) {
            v.x *= SCALE; v.y *= SCALE; v.z *= SCALE; v.w *= SCALE;
        } else if constexpr (MODE == EP_PROJ) {
            orow = remap_token(gr);
            float4 id = *(const float4*)&extra[(size_t)orow * EMBED + gc];
            v.x += id.x; v.y += id.y; v.z += id.z; v.w += id.w;
        } else if constexpr (MODE == EP_FC1) {
            v.x = gelu_exact(v.x); v.y = gelu_exact(v.y);
            v.z = gelu_exact(v.z); v.w = gelu_exact(v.w);
        } else if constexpr (MODE == EP_FC2) {
            const float* rsrc = g_xres;
            float4 rr = *(const float4*)&rsrc[(size_t)gr * EMBED + gc];
            v.x += rr.x; v.y += rr.y; v.z += rr.z; v.w += rr.w;
        }
        *(float4*)&outp[(size_t)orow * ldo + gc] = v;
    }
}

// ---------------- fused windowed attention (online softmax) ----------------
// one CTA per (window, head), 64 threads = one per query row
__global__ __launch_bounds__(64)
void attn_kernel(const float* __restrict__ relb)
{
    int head = blockIdx.x & (HEADS - 1);
    int win  = blockIdx.x >> 4;

    __shared__ __align__(16) float ks[64 * 36];
    __shared__ __align__(16) float vs[64 * 36];
    __shared__ float sbias[225];
    __shared__ int   lab[64];
    __shared__ int   crd[64];

    int n = threadIdx.x;
    const float* kp = &g_kv[((size_t)win * 64 + n) * 1024 + head * HD];
    #pragma unroll
    for (int q = 0; q < 8; q++) {
        *(float4*)&ks[n * 36 + q * 4] = *(const float4*)&kp[q * 4];
        *(float4*)&vs[n * 36 + q * 4] = *(const float4*)&kp[512 + q * 4];
    }
    float qreg[32];
    const float* qp = &g_qh[((size_t)win * 64 + n) * EMBED + head * HD];
    #pragma unroll
    for (int q = 0; q < 8; q++) {
        float4 t = *(const float4*)&qp[q * 4];
        qreg[q*4] = t.x; qreg[q*4+1] = t.y; qreg[q*4+2] = t.z; qreg[q*4+3] = t.w;
    }
    // rel-bias column for this head (225 entries)
    for (int i = n; i < 225; i += 64) sbias[i] = __ldg(&relb[i * HEADS + head]);
    // shift-mask region labels + rel-pos coords
    {
        int wi = win & 63, wr = wi >> 3, wc = wi & 7;
        int r = n >> 3, cc = n & 7;
        int grow = wr * 8 + r, gcol = wc * 8 + cc;
        int lh = (grow < 56) ? 0 : ((grow < 60) ? 1 : 2);
        int lw = (gcol < 56) ? 0 : ((gcol < 60) ? 1 : 2);
        lab[n] = lh * 3 + lw;
        crd[n] = r * 15 + cc;
    }
    __syncthreads();

    int myLab = lab[n], myC = crd[n];

    float m_run = -1e30f, l_run = 0.0f;
    float o[32];
    #pragma unroll
    for (int d = 0; d < 32; d++) o[d] = 0.0f;

    #pragma unroll
    for (int t = 0; t < 64; t += 16) {
        float s[16];
        float tmax = -1e30f;
        #pragma unroll
        for (int j = 0; j < 16; j++) {
            int m = t + j;
            float a = 0.0f;
            #pragma unroll
            for (int d = 0; d < 32; d += 4) {
                float4 kk = *(const float4*)&ks[m * 36 + d];
                a = fmaf(qreg[d],   kk.x, a);
                a = fmaf(qreg[d+1], kk.y, a);
                a = fmaf(qreg[d+2], kk.z, a);
                a = fmaf(qreg[d+3], kk.w, a);
            }
            a += sbias[myC + crd[63 - m]];
            if (lab[m] != myLab) a -= 100.0f;
            s[j] = a;
            tmax = fmaxf(tmax, a);
        }
        float nm = fmaxf(m_run, tmax);
        float corr = __expf(m_run - nm);
        l_run *= corr;
        #pragma unroll
        for (int d = 0; d < 32; d++) o[d] *= corr;
        #pragma unroll
        for (int j = 0; j < 16; j++) {
            float p = __expf(s[j] - nm);
            l_run += p;
            #pragma unroll
            for (int d = 0; d < 32; d += 4) {
                float4 vv = *(const float4*)&vs[(t + j) * 36 + d];
                o[d]   = fmaf(p, vv.x, o[d]);
                o[d+1] = fmaf(p, vv.y, o[d+1]);
                o[d+2] = fmaf(p, vv.z, o[d+2]);
                o[d+3] = fmaf(p, vv.w, o[d+3]);
            }
        }
        m_run = nm;
    }
    float inv = 1.0f / l_run;

    float* op = &g_att[((size_t)win * 64 + n) * EMBED + head * HD];
    #pragma unroll
    for (int d = 0; d < 32; d += 4) {
        float4 t4;
        t4.x = o[d] * inv; t4.y = o[d+1] * inv; t4.z = o[d+2] * inv; t4.w = o[d+3] * inv;
        *(float4*)&op[d] = t4;
    }
}

// ---------------- launch ----------------
extern "C" void kernel_launch(void* const* d_in, const int* in_sizes, int n_in,
                              void* d_out, int out_size)
{
    const float* x      = (const float*)d_in[0];
    const float* skip   = (const float*)d_in[1];
    const float* n1g    = (const float*)d_in[2];
    const float* n1b    = (const float*)d_in[3];
    const float* w_qkv  = (const float*)d_in[4];
    const float* b_qkv  = (const float*)d_in[5];
    const float* w_skip = (const float*)d_in[6];
    const float* b_skip = (const float*)d_in[7];
    const float* relb   = (const float*)d_in[8];
    const float* w_proj = (const float*)d_in[9];
    const float* b_proj = (const float*)d_in[10];
    const float* n2g    = (const float*)d_in[11];
    const float* n2b    = (const float*)d_in[12];
    const float* w_fc1  = (const float*)d_in[13];
    const float* b_fc1  = (const float*)d_in[14];
    const float* w_fc2  = (const float*)d_in[15];
    const float* b_fc2  = (const float*)d_in[16];
    float* out = (float*)d_out;

    cudaFuncSetAttribute(gemm_tf32<EP_KV>,   cudaFuncAttributeMaxDynamicSharedMemorySize, (int)GEMM_SMEM);
    cudaFuncSetAttribute(gemm_tf32<EP_QH>,   cudaFuncAttributeMaxDynamicSharedMemorySize, (int)GEMM_SMEM);
    cudaFuncSetAttribute(gemm_tf32<EP_PROJ>, cudaFuncAttributeMaxDynamicSharedMemorySize, (int)GEMM_SMEM);
    cudaFuncSetAttribute(gemm_tf32<EP_FC1>,  cudaFuncAttributeMaxDynamicSharedMemorySize, (int)GEMM_SMEM);
    cudaFuncSetAttribute(gemm_tf32<EP_FC2>,  cudaFuncAttributeMaxDynamicSharedMemorySize, (int)GEMM_SMEM);

    // 1) LN1 + shift-roll + window gather (x and skip)
    ln_kernel<true><<<dim3(TOK, 2), 128>>>(x, skip, n1g, n1b);
    // 2) kv = lnx @ w_qkv^T + b
    gemm_tf32<EP_KV><<<dim3(1024 / BN, TOK / BM), 256, GEMM_SMEM>>>(w_qkv, b_qkv, nullptr, nullptr, 512, 1024);
    // 3) q = (lns @ w_skip^T + b) * SCALE
    gemm_tf32<EP_QH><<<dim3(512 / BN, TOK / BM), 256, GEMM_SMEM>>>(w_skip, b_skip, nullptr, nullptr, 512, 512);
    // 4) fused attention per (window, head)
    attn_kernel<<<NWIN * HEADS, 64>>>(relb);
    // 5) proj + scatter back (inverse roll) + residual with original x
    gemm_tf32<EP_PROJ><<<dim3(512 / BN, TOK / BM), 256, GEMM_SMEM>>>(w_proj, b_proj, x, nullptr, 512, 512);
    // 6) LN2
    ln_kernel<false><<<dim3(TOK, 1), 128>>>(nullptr, nullptr, n2g, n2b);
    // 7) fc1 + exact GELU
    gemm_tf32<EP_FC1><<<dim3(FFN / BN, TOK / BM), 256, GEMM_SMEM>>>(w_fc1, b_fc1, nullptr, nullptr, 512, FFN);
    // 8) fc2 + residual -> d_out
    gemm_tf32<EP_FC2><<<dim3(512 / BN, TOK / BM), 256, GEMM_SMEM>>>(w_fc2, b_fc2, nullptr, out, FFN, 512);
}

// round 6
// speedup vs baseline: 3.3805x; 3.1260x over previous
#include <cuda_runtime.h>
#include <cuda_fp16.h>
#include <cstdint>
#include <math.h>

// ---------------- problem constants ----------------
#define TOK     65536          // 16 * 64 * 64 tokens
#define EMBED   512
#define HEADS   16
#define HD      32
#define FFN     2048
#define SHIFT   4
#define NWIN    1024
constexpr float SCALE = 0.17677669529663687f;   // 32^-0.5

// ---------------- device scratch ----------------
__device__ __align__(256) __half g_lnx [(size_t)TOK * EMBED];
__device__ __align__(256) __half g_lns [(size_t)TOK * EMBED];
__device__ __align__(256) float  g_kv  [(size_t)TOK * 2 * EMBED];
__device__ __align__(256) float  g_qh  [(size_t)TOK * EMBED];
__device__ __align__(256) __half g_att [(size_t)TOK * EMBED];
__device__ __align__(256) float  g_xres[(size_t)TOK * EMBED];
__device__ __align__(256) __half g_ln2 [(size_t)TOK * EMBED];
__device__ __align__(256) __half g_ffn [(size_t)TOK * FFN];

// half weight copies
__device__ __align__(256) __half h_wqkv[1024 * 512];
__device__ __align__(256) __half h_wskip[512 * 512];
__device__ __align__(256) __half h_wproj[512 * 512];
__device__ __align__(256) __half h_wfc1[2048 * 512];
__device__ __align__(256) __half h_wfc2[512 * 2048];

#include <mma.h>
using namespace nvcuda;

__device__ __forceinline__ int remap_token(int wt) {
    int win = wt >> 6, n = wt & 63;
    int b  = win >> 6, wi = win & 63;
    int wr = wi >> 3,  wc = wi & 7;
    int r  = n  >> 3,  cc = n  & 7;
    int grow = (wr * 8 + r  + SHIFT) & 63;
    int gcol = (wc * 8 + cc + SHIFT) & 63;
    return (b << 12) + (grow << 6) + gcol;
}

__device__ __forceinline__ void cp_async16(void* smem_dst, const void* gsrc) {
    unsigned s = (unsigned)__cvta_generic_to_shared(smem_dst);
    asm volatile("cp.async.cg.shared.global [%0], [%1], 16;\n" :: "r"(s), "l"(gsrc));
}

// ---------------- weight fp32 -> fp16 convert ----------------
__global__ __launch_bounds__(256)
void convert_kernel(const float* __restrict__ src, __half* __restrict__ dst, int n) {
    int i = (blockIdx.x * 256 + threadIdx.x) * 4;
    if (i < n) {
        float4 v = *(const float4*)&src[i];
        __half2 a = __floats2half2_rn(v.x, v.y);
        __half2 b = __floats2half2_rn(v.z, v.w);
        *(__half2*)&dst[i]     = a;
        *(__half2*)&dst[i + 2] = b;
    }
}

// ---------------- block reduce (128 threads) ----------------
__device__ __forceinline__ float blockReduce128(float v, float* red) {
    #pragma unroll
    for (int o = 16; o > 0; o >>= 1) v += __shfl_xor_sync(0xffffffffu, v, o);
    int lane = threadIdx.x & 31, w = threadIdx.x >> 5;
    if (lane == 0) red[w] = v;
    __syncthreads();
    float r = red[0] + red[1] + red[2] + red[3];
    __syncthreads();
    return r;
}

// ---------------- LayerNorm kernels (write fp16) ----------------
template<bool GATHER>
__global__ __launch_bounds__(128)
void ln_kernel(const float* __restrict__ src_x, const float* __restrict__ src_s,
               const float* __restrict__ g, const float* __restrict__ b)
{
    __shared__ float red[4];
    int wt = blockIdx.x;
    const float* src;
    __half* dst;
    if constexpr (GATHER) {
        int ot = remap_token(wt);
        src = (blockIdx.y == 0 ? src_x : src_s) + (size_t)ot * EMBED;
        dst = (blockIdx.y == 0 ? g_lnx : g_lns) + (size_t)wt * EMBED;
    } else {
        src = g_xres + (size_t)wt * EMBED;
        dst = g_ln2  + (size_t)wt * EMBED;
    }
    int t = threadIdx.x;
    float4 v = *(const float4*)&src[t * 4];
    float sum  = blockReduce128(v.x + v.y + v.z + v.w, red);
    float mean = sum * (1.0f / 512.0f);
    float dx = v.x - mean, dy = v.y - mean, dz = v.z - mean, dw = v.w - mean;
    float var = blockReduce128(dx*dx + dy*dy + dz*dz + dw*dw, red) * (1.0f / 512.0f);
    float rs = rsqrtf(var + 1e-5f);
    float4 gg = *(const float4*)&g[t * 4];
    float4 bb = *(const float4*)&b[t * 4];
    __half2 o0 = __floats2half2_rn(dx * rs * gg.x + bb.x, dy * rs * gg.y + bb.y);
    __half2 o1 = __floats2half2_rn(dz * rs * gg.z + bb.z, dw * rs * gg.w + bb.w);
    *(__half2*)&dst[t * 4]     = o0;
    *(__half2*)&dst[t * 4 + 2] = o1;
}

// ---------------- GEMM: fp16 wmma m16n16k16, cp.async double-buffered ----------------
// C[M,N] = A[M,K] * W[N,K]^T ; BM=128 BN=128 BK=32, 256 threads, warp tile 32x64
constexpr int BM = 128, BN = 128, BK = 32, APITCH = 40;   // halfs
constexpr int STAGE_HALFS = (BM + BN) * APITCH;           // 10240 halfs / stage (20KB)
constexpr size_t GEMM_SMEM = 64 * 1024;                   // max(2 stages 40KB, C 64KB)

enum { EP_KV = 0, EP_QH = 1, EP_PROJ = 2, EP_FC1 = 3, EP_FC2 = 4 };

__device__ __forceinline__ float gelu_exact(float x) {
    return 0.5f * x * (1.0f + erff(x * 0.7071067811865475f));
}

template<int MODE>
__global__ __launch_bounds__(256, 2)
void gemm_fp16(const __half* __restrict__ Bw, const float* __restrict__ bias,
               const float* __restrict__ extra, float* __restrict__ out_param,
               int K, int ldo)
{
    extern __shared__ __align__(16) __half smem[];

    const __half* A;
    if constexpr (MODE == EP_KV)        A = g_lnx;
    else if constexpr (MODE == EP_QH)   A = g_lns;
    else if constexpr (MODE == EP_PROJ) A = g_att;
    else if constexpr (MODE == EP_FC1)  A = g_ln2;
    else                                A = g_ffn;

    const int tid   = threadIdx.x;
    const int tileM = blockIdx.y * BM;
    const int tileN = blockIdx.x * BN;
    const int warp  = tid >> 5;
    const int wm    = warp >> 1;   // 0..3  -> rows wm*32
    const int wn    = warp & 1;    // 0..1  -> cols wn*64

    auto loadStage = [&](int s, int k0) {
        __half* sA = smem + s * STAGE_HALFS;
        __half* sB = sA + BM * APITCH;
        #pragma unroll
        for (int it = 0; it < 2; it++) {
            int idx = tid + it * 256;
            int row = idx >> 2, q = idx & 3;
            cp_async16(&sA[row * APITCH + q * 8],
                       &A[(size_t)(tileM + row) * K + k0 + q * 8]);
        }
        #pragma unroll
        for (int it = 0; it < 2; it++) {
            int idx = tid + it * 256;
            int row = idx >> 2, q = idx & 3;
            cp_async16(&sB[row * APITCH + q * 8],
                       &Bw[(size_t)(tileN + row) * K + k0 + q * 8]);
        }
        asm volatile("cp.async.commit_group;");
    };

    wmma::fragment<wmma::accumulator, 16, 16, 16, float> acc[2][4];
    #pragma unroll
    for (int i = 0; i < 2; i++)
        #pragma unroll
        for (int j = 0; j < 4; j++)
            wmma::fill_fragment(acc[i][j], 0.0f);

    const int nIter = K / BK;
    loadStage(0, 0);

    for (int i = 0; i < nIter; i++) {
        if (i + 1 < nIter) {
            loadStage((i + 1) & 1, (i + 1) * BK);
            asm volatile("cp.async.wait_group 1;");
        } else {
            asm volatile("cp.async.wait_group 0;");
        }
        __syncthreads();

        __half* sA = smem + (i & 1) * STAGE_HALFS;
        __half* sB = sA + BM * APITCH;

        #pragma unroll
        for (int kk = 0; kk < BK; kk += 16) {
            wmma::fragment<wmma::matrix_a, 16, 16, 16, __half, wmma::row_major> fa[2];
            wmma::fragment<wmma::matrix_b, 16, 16, 16, __half, wmma::col_major> fb[4];
            #pragma unroll
            for (int ii = 0; ii < 2; ii++)
                wmma::load_matrix_sync(fa[ii], &sA[(wm * 32 + ii * 16) * APITCH + kk], APITCH);
            #pragma unroll
            for (int j = 0; j < 4; j++)
                wmma::load_matrix_sync(fb[j], &sB[(wn * 64 + j * 16) * APITCH + kk], APITCH);
            #pragma unroll
            for (int ii = 0; ii < 2; ii++)
                #pragma unroll
                for (int j = 0; j < 4; j++)
                    wmma::mma_sync(acc[ii][j], fa[ii], fb[j], acc[ii][j]);
        }
        __syncthreads();
    }

    // ---- epilogue: stage C (128x128 fp32) in smem, then fused per-element op ----
    float* sC = (float*)smem;
    #pragma unroll
    for (int i = 0; i < 2; i++)
        #pragma unroll
        for (int j = 0; j < 4; j++)
            wmma::store_matrix_sync(&sC[(wm * 32 + i * 16) * BN + wn * 64 + j * 16],
                                    acc[i][j], BN, wmma::mem_row_major);
    __syncthreads();

    #pragma unroll
    for (int it = 0; it < 16; it++) {
        int idx = tid + it * 256;          // 0..4095 (float4 units)
        int row = idx >> 5;                // 0..127
        int col = (idx & 31) * 4;          // 0..124
        float4 v = *(float4*)&sC[row * BN + col];
        int gr = tileM + row;
        int gc = tileN + col;
        float4 bb = *(const float4*)&bias[gc];
        v.x += bb.x; v.y += bb.y; v.z += bb.z; v.w += bb.w;

        if constexpr (MODE == EP_KV) {
            *(float4*)&g_kv[(size_t)gr * 1024 + gc] = v;
        } else if constexpr (MODE == EP_QH) {
            v.x *= SCALE; v.y *= SCALE; v.z *= SCALE; v.w *= SCALE;
            *(float4*)&g_qh[(size_t)gr * EMBED + gc] = v;
        } else if constexpr (MODE == EP_PROJ) {
            int orow = remap_token(gr);
            float4 id = *(const float4*)&extra[(size_t)orow * EMBED + gc];
            v.x += id.x; v.y += id.y; v.z += id.z; v.w += id.w;
            *(float4*)&g_xres[(size_t)orow * EMBED + gc] = v;
        } else if constexpr (MODE == EP_FC1) {
            __half2 h0 = __floats2half2_rn(gelu_exact(v.x), gelu_exact(v.y));
            __half2 h1 = __floats2half2_rn(gelu_exact(v.z), gelu_exact(v.w));
            *(__half2*)&g_ffn[(size_t)gr * FFN + gc]     = h0;
            *(__half2*)&g_ffn[(size_t)gr * FFN + gc + 2] = h1;
        } else {  // EP_FC2
            float4 rr = *(const float4*)&g_xres[(size_t)gr * EMBED + gc];
            v.x += rr.x; v.y += rr.y; v.z += rr.z; v.w += rr.w;
            *(float4*)&out_param[(size_t)gr * EMBED + gc] = v;
        }
    }
}

// ---------------- fused windowed attention (online softmax, fp16 output) ----------------
__global__ __launch_bounds__(64)
void attn_kernel(const float* __restrict__ relb)
{
    int head = blockIdx.x & (HEADS - 1);
    int win  = blockIdx.x >> 4;

    __shared__ __align__(16) float ks[64 * 36];
    __shared__ __align__(16) float vs[64 * 36];
    __shared__ float sbias[225];
    __shared__ int   lab[64];
    __shared__ int   crd[64];

    int n = threadIdx.x;
    const float* kp = &g_kv[((size_t)win * 64 + n) * 1024 + head * HD];
    #pragma unroll
    for (int q = 0; q < 8; q++) {
        *(float4*)&ks[n * 36 + q * 4] = *(const float4*)&kp[q * 4];
        *(float4*)&vs[n * 36 + q * 4] = *(const float4*)&kp[512 + q * 4];
    }
    float qreg[32];
    const float* qp = &g_qh[((size_t)win * 64 + n) * EMBED + head * HD];
    #pragma unroll
    for (int q = 0; q < 8; q++) {
        float4 t = *(const float4*)&qp[q * 4];
        qreg[q*4] = t.x; qreg[q*4+1] = t.y; qreg[q*4+2] = t.z; qreg[q*4+3] = t.w;
    }
    for (int i = n; i < 225; i += 64) sbias[i] = __ldg(&relb[i * HEADS + head]);
    {
        int wi = win & 63, wr = wi >> 3, wc = wi & 7;
        int r = n >> 3, cc = n & 7;
        int grow = wr * 8 + r, gcol = wc * 8 + cc;
        int lh = (grow < 56) ? 0 : ((grow < 60) ? 1 : 2);
        int lw = (gcol < 56) ? 0 : ((gcol < 60) ? 1 : 2);
        lab[n] = lh * 3 + lw;
        crd[n] = r * 15 + cc;
    }
    __syncthreads();

    int myLab = lab[n], myC = crd[n];
    float m_run = -1e30f, l_run = 0.0f;
    float o[32];
    #pragma unroll
    for (int d = 0; d < 32; d++) o[d] = 0.0f;

    #pragma unroll
    for (int t = 0; t < 64; t += 16) {
        float s[16];
        float tmax = -1e30f;
        #pragma unroll
        for (int j = 0; j < 16; j++) {
            int m = t + j;
            float a = 0.0f;
            #pragma unroll
            for (int d = 0; d < 32; d += 4) {
                float4 kk = *(const float4*)&ks[m * 36 + d];
                a = fmaf(qreg[d],   kk.x, a);
                a = fmaf(qreg[d+1], kk.y, a);
                a = fmaf(qreg[d+2], kk.z, a);
                a = fmaf(qreg[d+3], kk.w, a);
            }
            a += sbias[myC + crd[63 - m]];
            if (lab[m] != myLab) a -= 100.0f;
            s[j] = a;
            tmax = fmaxf(tmax, a);
        }
        float nm = fmaxf(m_run, tmax);
        float corr = __expf(m_run - nm);
        l_run *= corr;
        #pragma unroll
        for (int d = 0; d < 32; d++) o[d] *= corr;
        #pragma unroll
        for (int j = 0; j < 16; j++) {
            float p = __expf(s[j] - nm);
            l_run += p;
            #pragma unroll
            for (int d = 0; d < 32; d += 4) {
                float4 vv = *(const float4*)&vs[(t + j) * 36 + d];
                o[d]   = fmaf(p, vv.x, o[d]);
                o[d+1] = fmaf(p, vv.y, o[d+1]);
                o[d+2] = fmaf(p, vv.z, o[d+2]);
                o[d+3] = fmaf(p, vv.w, o[d+3]);
            }
        }
        m_run = nm;
    }
    float inv = 1.0f / l_run;

    __half* op = &g_att[((size_t)win * 64 + n) * EMBED + head * HD];
    #pragma unroll
    for (int d = 0; d < 32; d += 2) {
        *(__half2*)&op[d] = __floats2half2_rn(o[d] * inv, o[d+1] * inv);
    }
}

// ---------------- launch ----------------
extern "C" void kernel_launch(void* const* d_in, const int* in_sizes, int n_in,
                              void* d_out, int out_size)
{
    const float* x      = (const float*)d_in[0];
    const float* skip   = (const float*)d_in[1];
    const float* n1g    = (const float*)d_in[2];
    const float* n1b    = (const float*)d_in[3];
    const float* w_qkv  = (const float*)d_in[4];
    const float* b_qkv  = (const float*)d_in[5];
    const float* w_skip = (const float*)d_in[6];
    const float* b_skip = (const float*)d_in[7];
    const float* relb   = (const float*)d_in[8];
    const float* w_proj = (const float*)d_in[9];
    const float* b_proj = (const float*)d_in[10];
    const float* n2g    = (const float*)d_in[11];
    const float* n2b    = (const float*)d_in[12];
    const float* w_fc1  = (const float*)d_in[13];
    const float* b_fc1  = (const float*)d_in[14];
    const float* w_fc2  = (const float*)d_in[15];
    const float* b_fc2  = (const float*)d_in[16];
    float* out = (float*)d_out;

    cudaFuncSetAttribute(gemm_fp16<EP_KV>,   cudaFuncAttributeMaxDynamicSharedMemorySize, (int)GEMM_SMEM);
    cudaFuncSetAttribute(gemm_fp16<EP_QH>,   cudaFuncAttributeMaxDynamicSharedMemorySize, (int)GEMM_SMEM);
    cudaFuncSetAttribute(gemm_fp16<EP_PROJ>, cudaFuncAttributeMaxDynamicSharedMemorySize, (int)GEMM_SMEM);
    cudaFuncSetAttribute(gemm_fp16<EP_FC1>,  cudaFuncAttributeMaxDynamicSharedMemorySize, (int)GEMM_SMEM);
    cudaFuncSetAttribute(gemm_fp16<EP_FC2>,  cudaFuncAttributeMaxDynamicSharedMemorySize, (int)GEMM_SMEM);

    // 0) weight conversions (fp32 -> fp16)
    __half *dwq, *dws, *dwp, *dw1, *dw2;
    cudaGetSymbolAddress((void**)&dwq, h_wqkv);
    cudaGetSymbolAddress((void**)&dws, h_wskip);
    cudaGetSymbolAddress((void**)&dwp, h_wproj);
    cudaGetSymbolAddress((void**)&dw1, h_wfc1);
    cudaGetSymbolAddress((void**)&dw2, h_wfc2);
    convert_kernel<<<(1024 * 512 / 4 + 255) / 256, 256>>>(w_qkv,  dwq, 1024 * 512);
    convert_kernel<<<(512 * 512 / 4 + 255) / 256, 256>>>(w_skip, dws, 512 * 512);
    convert_kernel<<<(512 * 512 / 4 + 255) / 256, 256>>>(w_proj, dwp, 512 * 512);
    convert_kernel<<<(2048 * 512 / 4 + 255) / 256, 256>>>(w_fc1,  dw1, 2048 * 512);
    convert_kernel<<<(512 * 2048 / 4 + 255) / 256, 256>>>(w_fc2,  dw2, 512 * 2048);

    // 1) LN1 + shift-roll + window gather (x and skip)
    ln_kernel<true><<<dim3(TOK, 2), 128>>>(x, skip, n1g, n1b);
    // 2) kv = lnx @ w_qkv^T + b
    gemm_fp16<EP_KV><<<dim3(1024 / BN, TOK / BM), 256, GEMM_SMEM>>>(dwq, b_qkv, nullptr, nullptr, 512, 1024);
    // 3) q = (lns @ w_skip^T + b) * SCALE
    gemm_fp16<EP_QH><<<dim3(512 / BN, TOK / BM), 256, GEMM_SMEM>>>(dws, b_skip, nullptr, nullptr, 512, 512);
    // 4) fused attention per (window, head)
    attn_kernel<<<NWIN * HEADS, 64>>>(relb);
    // 5) proj + scatter back (inverse roll) + residual with original x
    gemm_fp16<EP_PROJ><<<dim3(512 / BN, TOK / BM), 256, GEMM_SMEM>>>(dwp, b_proj, x, nullptr, 512, 512);
    // 6) LN2
    ln_kernel<false><<<dim3(TOK, 1), 128>>>(nullptr, nullptr, n2g, n2b);
    // 7) fc1 + exact GELU
    gemm_fp16<EP_FC1><<<dim3(FFN / BN, TOK / BM), 256, GEMM_SMEM>>>(dw1, b_fc1, nullptr, nullptr, 512, FFN);
    // 8) fc2 + residual -> d_out
    gemm_fp16<EP_FC2><<<dim3(512 / BN, TOK / BM), 256, GEMM_SMEM>>>(dw2, b_fc2, nullptr, out, 2048, 512);
}

// round 7
// speedup vs baseline: 3.5039x; 1.0365x over previous
#include <cuda_runtime.h>
#include <cuda_fp16.h>
#include <cstdint>
#include <math.h>

// ---------------- problem constants ----------------
#define TOK     65536          // 16 * 64 * 64 tokens
#define EMBED   512
#define HEADS   16
#define HD      32
#define FFN     2048
#define SHIFT   4
#define NWIN    1024
constexpr float SCALE = 0.17677669529663687f;   // 32^-0.5

// ---------------- device scratch ----------------
__device__ __align__(256) __half g_lnx [(size_t)TOK * EMBED];
__device__ __align__(256) __half g_lns [(size_t)TOK * EMBED];
__device__ __align__(256) __half g_kv  [(size_t)TOK * 2 * EMBED];
__device__ __align__(256) __half g_qh  [(size_t)TOK * EMBED];
__device__ __align__(256) __half g_att [(size_t)TOK * EMBED];
__device__ __align__(256) float  g_xres[(size_t)TOK * EMBED];
__device__ __align__(256) __half g_ln2 [(size_t)TOK * EMBED];
__device__ __align__(256) __half g_ffn [(size_t)TOK * FFN];

// half weight copies
__device__ __align__(256) __half h_wqkv[1024 * 512];
__device__ __align__(256) __half h_wskip[512 * 512];
__device__ __align__(256) __half h_wproj[512 * 512];
__device__ __align__(256) __half h_wfc1[2048 * 512];
__device__ __align__(256) __half h_wfc2[512 * 2048];

#include <mma.h>
using namespace nvcuda;

__device__ __forceinline__ int remap_token(int wt) {
    int win = wt >> 6, n = wt & 63;
    int b  = win >> 6, wi = win & 63;
    int wr = wi >> 3,  wc = wi & 7;
    int r  = n  >> 3,  cc = n  & 7;
    int grow = (wr * 8 + r  + SHIFT) & 63;
    int gcol = (wc * 8 + cc + SHIFT) & 63;
    return (b << 12) + (grow << 6) + gcol;
}

__device__ __forceinline__ void cp_async16(void* smem_dst, const void* gsrc) {
    unsigned s = (unsigned)__cvta_generic_to_shared(smem_dst);
    asm volatile("cp.async.cg.shared.global [%0], [%1], 16;\n" :: "r"(s), "l"(gsrc));
}

// ---------------- weight fp32 -> fp16 convert ----------------
__global__ __launch_bounds__(256)
void convert_kernel(const float* __restrict__ src, __half* __restrict__ dst, int n) {
    int i = (blockIdx.x * 256 + threadIdx.x) * 4;
    if (i < n) {
        float4 v = *(const float4*)&src[i];
        *(__half2*)&dst[i]     = __floats2half2_rn(v.x, v.y);
        *(__half2*)&dst[i + 2] = __floats2half2_rn(v.z, v.w);
    }
}

// ---------------- block reduce (128 threads) ----------------
__device__ __forceinline__ float blockReduce128(float v, float* red) {
    #pragma unroll
    for (int o = 16; o > 0; o >>= 1) v += __shfl_xor_sync(0xffffffffu, v, o);
    int lane = threadIdx.x & 31, w = threadIdx.x >> 5;
    if (lane == 0) red[w] = v;
    __syncthreads();
    float r = red[0] + red[1] + red[2] + red[3];
    __syncthreads();
    return r;
}

// ---------------- LayerNorm kernels (write fp16) ----------------
template<bool GATHER>
__global__ __launch_bounds__(128)
void ln_kernel(const float* __restrict__ src_x, const float* __restrict__ src_s,
               const float* __restrict__ g, const float* __restrict__ b)
{
    __shared__ float red[4];
    int wt = blockIdx.x;
    const float* src;
    __half* dst;
    if constexpr (GATHER) {
        int ot = remap_token(wt);
        src = (blockIdx.y == 0 ? src_x : src_s) + (size_t)ot * EMBED;
        dst = (blockIdx.y == 0 ? g_lnx : g_lns) + (size_t)wt * EMBED;
    } else {
        src = g_xres + (size_t)wt * EMBED;
        dst = g_ln2  + (size_t)wt * EMBED;
    }
    int t = threadIdx.x;
    float4 v = *(const float4*)&src[t * 4];
    float sum  = blockReduce128(v.x + v.y + v.z + v.w, red);
    float mean = sum * (1.0f / 512.0f);
    float dx = v.x - mean, dy = v.y - mean, dz = v.z - mean, dw = v.w - mean;
    float var = blockReduce128(dx*dx + dy*dy + dz*dz + dw*dw, red) * (1.0f / 512.0f);
    float rs = rsqrtf(var + 1e-5f);
    float4 gg = *(const float4*)&g[t * 4];
    float4 bb = *(const float4*)&b[t * 4];
    *(__half2*)&dst[t * 4]     = __floats2half2_rn(dx * rs * gg.x + bb.x, dy * rs * gg.y + bb.y);
    *(__half2*)&dst[t * 4 + 2] = __floats2half2_rn(dz * rs * gg.z + bb.z, dw * rs * gg.w + bb.w);
}

// ---------------- GEMM: fp16 wmma m16n16k16, 64x64 warp tile ----------------
// C[M,N] = A[M,K] * W[N,K]^T ; BM=128 BN=128 BK=32, 128 threads (4 warps 2x2)
constexpr int BM = 128, BN = 128, BK = 32, APITCH = 40;   // halfs
constexpr int STAGE_HALFS = (BM + BN) * APITCH;           // 10240 halfs / stage (20KB)
constexpr size_t GEMM_SMEM = 64 * 1024;                   // max(2 stages 40KB, C 64KB)

enum { EP_KV = 0, EP_QH = 1, EP_PROJ = 2, EP_FC1 = 3, EP_FC2 = 4 };

__device__ __forceinline__ float gelu_exact(float x) {
    return 0.5f * x * (1.0f + erff(x * 0.7071067811865475f));
}

template<int MODE>
__global__ __launch_bounds__(128, 2)
void gemm_fp16(const __half* __restrict__ Bw, const float* __restrict__ bias,
               const float* __restrict__ extra, float* __restrict__ out_param,
               int K, int ldo)
{
    extern __shared__ __align__(16) __half smem[];

    const __half* A;
    if constexpr (MODE == EP_KV)        A = g_lnx;
    else if constexpr (MODE == EP_QH)   A = g_lns;
    else if constexpr (MODE == EP_PROJ) A = g_att;
    else if constexpr (MODE == EP_FC1)  A = g_ln2;
    else                                A = g_ffn;

    const int tid   = threadIdx.x;
    const int tileM = blockIdx.y * BM;
    const int tileN = blockIdx.x * BN;
    const int warp  = tid >> 5;
    const int wm    = warp >> 1;   // 0..1  -> rows wm*64
    const int wn    = warp & 1;    // 0..1  -> cols wn*64

    auto loadStage = [&](int s, int k0) {
        __half* sA = smem + s * STAGE_HALFS;
        __half* sB = sA + BM * APITCH;
        #pragma unroll
        for (int it = 0; it < 4; it++) {
            int idx = tid + it * 128;
            int row = idx >> 2, q = idx & 3;
            cp_async16(&sA[row * APITCH + q * 8],
                       &A[(size_t)(tileM + row) * K + k0 + q * 8]);
        }
        #pragma unroll
        for (int it = 0; it < 4; it++) {
            int idx = tid + it * 128;
            int row = idx >> 2, q = idx & 3;
            cp_async16(&sB[row * APITCH + q * 8],
                       &Bw[(size_t)(tileN + row) * K + k0 + q * 8]);
        }
        asm volatile("cp.async.commit_group;");
    };

    wmma::fragment<wmma::accumulator, 16, 16, 16, float> acc[4][4];
    #pragma unroll
    for (int i = 0; i < 4; i++)
        #pragma unroll
        for (int j = 0; j < 4; j++)
            wmma::fill_fragment(acc[i][j], 0.0f);

    const int nIter = K / BK;
    loadStage(0, 0);

    for (int i = 0; i < nIter; i++) {
        if (i + 1 < nIter) {
            loadStage((i + 1) & 1, (i + 1) * BK);
            asm volatile("cp.async.wait_group 1;");
        } else {
            asm volatile("cp.async.wait_group 0;");
        }
        __syncthreads();

        __half* sA = smem + (i & 1) * STAGE_HALFS;
        __half* sB = sA + BM * APITCH;

        #pragma unroll
        for (int kk = 0; kk < BK; kk += 16) {
            wmma::fragment<wmma::matrix_a, 16, 16, 16, __half, wmma::row_major> fa[4];
            wmma::fragment<wmma::matrix_b, 16, 16, 16, __half, wmma::col_major> fb[4];
            #pragma unroll
            for (int ii = 0; ii < 4; ii++)
                wmma::load_matrix_sync(fa[ii], &sA[(wm * 64 + ii * 16) * APITCH + kk], APITCH);
            #pragma unroll
            for (int j = 0; j < 4; j++)
                wmma::load_matrix_sync(fb[j], &sB[(wn * 64 + j * 16) * APITCH + kk], APITCH);
            #pragma unroll
            for (int ii = 0; ii < 4; ii++)
                #pragma unroll
                for (int j = 0; j < 4; j++)
                    wmma::mma_sync(acc[ii][j], fa[ii], fb[j], acc[ii][j]);
        }
        __syncthreads();
    }

    // ---- epilogue: stage C (128x128 fp32) in smem, then fused per-element op ----
    float* sC = (float*)smem;
    #pragma unroll
    for (int i = 0; i < 4; i++)
        #pragma unroll
        for (int j = 0; j < 4; j++)
            wmma::store_matrix_sync(&sC[(wm * 64 + i * 16) * BN + wn * 64 + j * 16],
                                    acc[i][j], BN, wmma::mem_row_major);
    __syncthreads();

    #pragma unroll
    for (int it = 0; it < 32; it++) {
        int idx = tid + it * 128;          // 0..4095 (float4 units)
        int row = idx >> 5;                // 0..127
        int col = (idx & 31) * 4;          // 0..124
        float4 v = *(float4*)&sC[row * BN + col];
        int gr = tileM + row;
        int gc = tileN + col;
        float4 bb = *(const float4*)&bias[gc];
        v.x += bb.x; v.y += bb.y; v.z += bb.z; v.w += bb.w;

        if constexpr (MODE == EP_KV) {
            *(__half2*)&g_kv[(size_t)gr * 1024 + gc]     = __floats2half2_rn(v.x, v.y);
            *(__half2*)&g_kv[(size_t)gr * 1024 + gc + 2] = __floats2half2_rn(v.z, v.w);
        } else if constexpr (MODE == EP_QH) {
            *(__half2*)&g_qh[(size_t)gr * EMBED + gc]     = __floats2half2_rn(v.x * SCALE, v.y * SCALE);
            *(__half2*)&g_qh[(size_t)gr * EMBED + gc + 2] = __floats2half2_rn(v.z * SCALE, v.w * SCALE);
        } else if constexpr (MODE == EP_PROJ) {
            int orow = remap_token(gr);
            float4 id = *(const float4*)&extra[(size_t)orow * EMBED + gc];
            v.x += id.x; v.y += id.y; v.z += id.z; v.w += id.w;
            *(float4*)&g_xres[(size_t)orow * EMBED + gc] = v;
        } else if constexpr (MODE == EP_FC1) {
            *(__half2*)&g_ffn[(size_t)gr * FFN + gc]     = __floats2half2_rn(gelu_exact(v.x), gelu_exact(v.y));
            *(__half2*)&g_ffn[(size_t)gr * FFN + gc + 2] = __floats2half2_rn(gelu_exact(v.z), gelu_exact(v.w));
        } else {  // EP_FC2
            float4 rr = *(const float4*)&g_xres[(size_t)gr * EMBED + gc];
            v.x += rr.x; v.y += rr.y; v.z += rr.z; v.w += rr.w;
            *(float4*)&out_param[(size_t)gr * EMBED + gc] = v;
        }
    }
}

// ---------------- fused windowed attention (online softmax, fp16 I/O) ----------------
__global__ __launch_bounds__(64)
void attn_kernel(const float* __restrict__ relb)
{
    int head = blockIdx.x & (HEADS - 1);
    int win  = blockIdx.x >> 4;

    __shared__ __align__(16) float ks[64 * 36];
    __shared__ __align__(16) float vs[64 * 36];
    __shared__ float sbias[225];
    __shared__ int   lab[64];
    __shared__ int   crd[64];

    int n = threadIdx.x;
    const __half* kp = &g_kv[((size_t)win * 64 + n) * 1024 + head * HD];
    #pragma unroll
    for (int q = 0; q < 4; q++) {                       // 4 x 8 halfs = 32 (K)
        uint4 u = *(const uint4*)&kp[q * 8];
        float2 f0 = __half22float2(*(__half2*)&u.x);
        float2 f1 = __half22float2(*(__half2*)&u.y);
        float2 f2 = __half22float2(*(__half2*)&u.z);
        float2 f3 = __half22float2(*(__half2*)&u.w);
        float* kd = &ks[n * 36 + q * 8];
        kd[0]=f0.x; kd[1]=f0.y; kd[2]=f1.x; kd[3]=f1.y;
        kd[4]=f2.x; kd[5]=f2.y; kd[6]=f3.x; kd[7]=f3.y;
        uint4 w = *(const uint4*)&kp[512 + q * 8];      // V
        float2 g0 = __half22float2(*(__half2*)&w.x);
        float2 g1 = __half22float2(*(__half2*)&w.y);
        float2 g2 = __half22float2(*(__half2*)&w.z);
        float2 g3 = __half22float2(*(__half2*)&w.w);
        float* vd = &vs[n * 36 + q * 8];
        vd[0]=g0.x; vd[1]=g0.y; vd[2]=g1.x; vd[3]=g1.y;
        vd[4]=g2.x; vd[5]=g2.y; vd[6]=g3.x; vd[7]=g3.y;
    }
    float qreg[32];
    const __half* qp = &g_qh[((size_t)win * 64 + n) * EMBED + head * HD];
    #pragma unroll
    for (int q = 0; q < 4; q++) {
        uint4 u = *(const uint4*)&qp[q * 8];
        float2 f0 = __half22float2(*(__half2*)&u.x);
        float2 f1 = __half22float2(*(__half2*)&u.y);
        float2 f2 = __half22float2(*(__half2*)&u.z);
        float2 f3 = __half22float2(*(__half2*)&u.w);
        qreg[q*8]=f0.x;   qreg[q*8+1]=f0.y; qreg[q*8+2]=f1.x; qreg[q*8+3]=f1.y;
        qreg[q*8+4]=f2.x; qreg[q*8+5]=f2.y; qreg[q*8+6]=f3.x; qreg[q*8+7]=f3.y;
    }
    for (int i = n; i < 225; i += 64) sbias[i] = __ldg(&relb[i * HEADS + head]);
    {
        int wi = win & 63, wr = wi >> 3, wc = wi & 7;
        int r = n >> 3, cc = n & 7;
        int grow = wr * 8 + r, gcol = wc * 8 + cc;
        int lh = (grow < 56) ? 0 : ((grow < 60) ? 1 : 2);
        int lw = (gcol < 56) ? 0 : ((gcol < 60) ? 1 : 2);
        lab[n] = lh * 3 + lw;
        crd[n] = r * 15 + cc;
    }
    __syncthreads();

    int myLab = lab[n], myC = crd[n];
    float m_run = -1e30f, l_run = 0.0f;
    float o[32];
    #pragma unroll
    for (int d = 0; d < 32; d++) o[d] = 0.0f;

    #pragma unroll
    for (int t = 0; t < 64; t += 16) {
        float s[16];
        float tmax = -1e30f;
        #pragma unroll
        for (int j = 0; j < 16; j++) {
            int m = t + j;
            float a = 0.0f;
            #pragma unroll
            for (int d = 0; d < 32; d += 4) {
                float4 kk = *(const float4*)&ks[m * 36 + d];
                a = fmaf(qreg[d],   kk.x, a);
                a = fmaf(qreg[d+1], kk.y, a);
                a = fmaf(qreg[d+2], kk.z, a);
                a = fmaf(qreg[d+3], kk.w, a);
            }
            a += sbias[myC + crd[63 - m]];
            if (lab[m] != myLab) a -= 100.0f;
            s[j] = a;
            tmax = fmaxf(tmax, a);
        }
        float nm = fmaxf(m_run, tmax);
        float corr = __expf(m_run - nm);
        l_run *= corr;
        #pragma unroll
        for (int d = 0; d < 32; d++) o[d] *= corr;
        #pragma unroll
        for (int j = 0; j < 16; j++) {
            float p = __expf(s[j] - nm);
            l_run += p;
            #pragma unroll
            for (int d = 0; d < 32; d += 4) {
                float4 vv = *(const float4*)&vs[(t + j) * 36 + d];
                o[d]   = fmaf(p, vv.x, o[d]);
                o[d+1] = fmaf(p, vv.y, o[d+1]);
                o[d+2] = fmaf(p, vv.z, o[d+2]);
                o[d+3] = fmaf(p, vv.w, o[d+3]);
            }
        }
        m_run = nm;
    }
    float inv = 1.0f / l_run;

    __half* op = &g_att[((size_t)win * 64 + n) * EMBED + head * HD];
    #pragma unroll
    for (int d = 0; d < 32; d += 2) {
        *(__half2*)&op[d] = __floats2half2_rn(o[d] * inv, o[d+1] * inv);
    }
}

// ---------------- launch ----------------
extern "C" void kernel_launch(void* const* d_in, const int* in_sizes, int n_in,
                              void* d_out, int out_size)
{
    const float* x      = (const float*)d_in[0];
    const float* skip   = (const float*)d_in[1];
    const float* n1g    = (const float*)d_in[2];
    const float* n1b    = (const float*)d_in[3];
    const float* w_qkv  = (const float*)d_in[4];
    const float* b_qkv  = (const float*)d_in[5];
    const float* w_skip = (const float*)d_in[6];
    const float* b_skip = (const float*)d_in[7];
    const float* relb   = (const float*)d_in[8];
    const float* w_proj = (const float*)d_in[9];
    const float* b_proj = (const float*)d_in[10];
    const float* n2g    = (const float*)d_in[11];
    const float* n2b    = (const float*)d_in[12];
    const float* w_fc1  = (const float*)d_in[13];
    const float* b_fc1  = (const float*)d_in[14];
    const float* w_fc2  = (const float*)d_in[15];
    const float* b_fc2  = (const float*)d_in[16];
    float* out = (float*)d_out;

    cudaFuncSetAttribute(gemm_fp16<EP_KV>,   cudaFuncAttributeMaxDynamicSharedMemorySize, (int)GEMM_SMEM);
    cudaFuncSetAttribute(gemm_fp16<EP_QH>,   cudaFuncAttributeMaxDynamicSharedMemorySize, (int)GEMM_SMEM);
    cudaFuncSetAttribute(gemm_fp16<EP_PROJ>, cudaFuncAttributeMaxDynamicSharedMemorySize, (int)GEMM_SMEM);
    cudaFuncSetAttribute(gemm_fp16<EP_FC1>,  cudaFuncAttributeMaxDynamicSharedMemorySize, (int)GEMM_SMEM);
    cudaFuncSetAttribute(gemm_fp16<EP_FC2>,  cudaFuncAttributeMaxDynamicSharedMemorySize, (int)GEMM_SMEM);

    // 0) weight conversions (fp32 -> fp16)
    __half *dwq, *dws, *dwp, *dw1, *dw2;
    cudaGetSymbolAddress((void**)&dwq, h_wqkv);
    cudaGetSymbolAddress((void**)&dws, h_wskip);
    cudaGetSymbolAddress((void**)&dwp, h_wproj);
    cudaGetSymbolAddress((void**)&dw1, h_wfc1);
    cudaGetSymbolAddress((void**)&dw2, h_wfc2);
    convert_kernel<<<(1024 * 512 / 4 + 255) / 256, 256>>>(w_qkv,  dwq, 1024 * 512);
    convert_kernel<<<(512 * 512 / 4 + 255) / 256, 256>>>(w_skip, dws, 512 * 512);
    convert_kernel<<<(512 * 512 / 4 + 255) / 256, 256>>>(w_proj, dwp, 512 * 512);
    convert_kernel<<<(2048 * 512 / 4 + 255) / 256, 256>>>(w_fc1,  dw1, 2048 * 512);
    convert_kernel<<<(512 * 2048 / 4 + 255) / 256, 256>>>(w_fc2,  dw2, 512 * 2048);

    // 1) LN1 + shift-roll + window gather (x and skip)
    ln_kernel<true><<<dim3(TOK, 2), 128>>>(x, skip, n1g, n1b);
    // 2) kv = lnx @ w_qkv^T + b
    gemm_fp16<EP_KV><<<dim3(1024 / BN, TOK / BM), 128, GEMM_SMEM>>>(dwq, b_qkv, nullptr, nullptr, 512, 1024);
    // 3) q = (lns @ w_skip^T + b) * SCALE
    gemm_fp16<EP_QH><<<dim3(512 / BN, TOK / BM), 128, GEMM_SMEM>>>(dws, b_skip, nullptr, nullptr, 512, 512);
    // 4) fused attention per (window, head)
    attn_kernel<<<NWIN * HEADS, 64>>>(relb);
    // 5) proj + scatter back (inverse roll) + residual with original x
    gemm_fp16<EP_PROJ><<<dim3(512 / BN, TOK / BM), 128, GEMM_SMEM>>>(dwp, b_proj, x, nullptr, 512, 512);
    // 6) LN2
    ln_kernel<false><<<dim3(TOK, 1), 128>>>(nullptr, nullptr, n2g, n2b);
    // 7) fc1 + exact GELU
    gemm_fp16<EP_FC1><<<dim3(FFN / BN, TOK / BM), 128, GEMM_SMEM>>>(dw1, b_fc1, nullptr, nullptr, 512, FFN);
    // 8) fc2 + residual -> d_out
    gemm_fp16<EP_FC2><<<dim3(512 / BN, TOK / BM), 128, GEMM_SMEM>>>(dw2, b_fc2, nullptr, out, 2048, 512);
}